// round 7
// baseline (speedup 1.0000x reference)
#include <cuda_runtime.h>
#include <cuda_bf16.h>
#include <mma.h>
#include <math.h>
#include <cstdint>

using namespace nvcuda;

// Problem constants
#define NN 50000
#define NE 800000
#define F  128
#define R  8
#define NKEY (NN * R)                // 400000 (dst,rel) buckets
#define NB  ((NKEY + 1023) / 1024)   // 391 scan blocks

// GEMM tile config
#define PAD 144                       // bf16 elems per smem row (288B, 16B-aligned rows)
#define TB  (128 * PAD * 2)           // bytes per tile (36864)
#define GEMM_SMEM (4 * TB)            // A0 B0 A1 B1 = 147456

// ---------------- device scratch (no cudaMalloc allowed) ----------------
__device__ __nv_bfloat16 g_T[(size_t)NN * R * F];   // per-(node,rel) sums, bf16 [NKEY][128]
__device__ __nv_bfloat16 g_h1[(size_t)NN * F];      // layer-1 output (bf16)
__device__ __nv_bfloat16 g_hbf[(size_t)NN * F];     // bf16 copy of input features
__device__ __nv_bfloat16 g_Wb1[9 * F * F];          // W1 blocks 0..7 + W1_self (bf16)
__device__ __nv_bfloat16 g_Wb2[9 * F * F];          // W2 blocks 0..7 + W2_self (bf16)
__device__ int   g_deg2[NKEY];
__device__ int   g_off2[NKEY + 1];
__device__ int   g_cur2[NKEY];
__device__ int   g_esrc[NE];                        // src sorted by (dst, rel)
__device__ float g_pool[F];
// chained-scan state (re-zeroed by k_setup on every replay)
__device__ volatile int g_scanval[NB];
__device__ volatile int g_scanflag[NB];

// ---------------- cp.async helpers ----------------
__device__ __forceinline__ void cp_async16(void* sdst, const void* gsrc, int src_bytes) {
    unsigned s = (unsigned)__cvta_generic_to_shared(sdst);
    asm volatile("cp.async.cg.shared.global [%0], [%1], 16, %2;\n"
                 :: "r"(s), "l"(gsrc), "r"(src_bytes));
}
#define CP_COMMIT() asm volatile("cp.async.commit_group;\n" ::: "memory")
#define CP_WAIT(N)  asm volatile("cp.async.wait_group %0;\n" :: "n"(N) : "memory")

// ---------------- fused setup: zero CSR state + fp32->bf16 converts ----------------
#define NZ_BLK ((NKEY + 255) / 256)              // 1563+? = 1563? -> compute exactly
#define NC_BLK ((NN * F / 4 + 255) / 256)        // 6250
#define NW_ELEM (9 * F * F / 4)                  // 36864 float4 groups
#define NW_BLK ((NW_ELEM + 255) / 256)           // 144

__global__ void __launch_bounds__(256)
k_setup(const float* __restrict__ in_feat,
        const float* __restrict__ W1, const float* __restrict__ W1s,
        const float* __restrict__ W2, const float* __restrict__ W2s) {
    int b = blockIdx.x;
    int t = threadIdx.x;
    if (b < NZ_BLK) {
        int i = b * 256 + t;
        if (i < NKEY) g_deg2[i] = 0;
        if (i < F)    g_pool[i] = 0.f;
        if (i < NB)   { g_scanflag[i] = 0; g_scanval[i] = 0; }
        return;
    }
    b -= NZ_BLK;
    if (b < NC_BLK) {
        int i = b * 256 + t;
        if (i >= NN * F / 4) return;
        float4 v = ((const float4*)in_feat)[i];
        __nv_bfloat162 p0 = __floats2bfloat162_rn(v.x, v.y);
        __nv_bfloat162 p1 = __floats2bfloat162_rn(v.z, v.w);
        uint2 o; o.x = *(unsigned*)&p0; o.y = *(unsigned*)&p1;
        ((uint2*)g_hbf)[i] = o;
        return;
    }
    b -= NC_BLK;
    // weight converts: first NW_BLK blocks -> W1, next NW_BLK -> W2
    int which = (b < NW_BLK) ? 0 : 1;
    if (which) b -= NW_BLK;
    int i = b * 256 + t;
    if (i >= NW_ELEM) return;
    const float* W  = which ? W2  : W1;
    const float* Ws = which ? W2s : W1s;
    const float4* src = (i < 8 * F * F / 4) ? ((const float4*)W + i)
                                            : ((const float4*)Ws + (i - 8 * F * F / 4));
    float4 v = *src;
    __nv_bfloat162 p0 = __floats2bfloat162_rn(v.x, v.y);
    __nv_bfloat162 p1 = __floats2bfloat162_rn(v.z, v.w);
    uint2 o; o.x = *(unsigned*)&p0; o.y = *(unsigned*)&p1;
    ((uint2*)(which == 0 ? g_Wb1 : g_Wb2))[i] = o;
}
#define SETUP_GRID (NZ_BLK + NC_BLK + 2 * NW_BLK)

// ---------------- CSR build ----------------
__global__ void k_hist(const int* __restrict__ dst, const int* __restrict__ et) {
    int e = blockIdx.x * blockDim.x + threadIdx.x;
    if (e < NE) atomicAdd(&g_deg2[dst[e] * 8 + et[e]], 1);
}

// single-pass decoupled-chained scan: deterministic, 391 blocks x 1024 threads
__global__ void __launch_bounds__(1024) k_scan() {
    __shared__ int ws[32];
    __shared__ int s_prev;
    int b = blockIdx.x, t = threadIdx.x;
    int lane = t & 31, wid = t >> 5;
    int i = b * 1024 + t;
    int v = (i < NKEY) ? g_deg2[i] : 0;
    int x = v;
    #pragma unroll
    for (int o = 1; o < 32; o <<= 1) { int u = __shfl_up_sync(~0u, x, o); if (lane >= o) x += u; }
    if (lane == 31) ws[wid] = x;
    __syncthreads();
    if (wid == 0) {
        int s = ws[lane];
        #pragma unroll
        for (int o = 1; o < 32; o <<= 1) { int u = __shfl_up_sync(~0u, s, o); if (lane >= o) s += u; }
        ws[lane] = s;
    }
    __syncthreads();
    int excl = x - v + (wid > 0 ? ws[wid - 1] : 0);
    int total = ws[31];
    // chain: wait for predecessor's inclusive prefix
    if (t == 0) {
        int prev = 0;
        if (b > 0) {
            while (g_scanflag[b - 1] == 0) __nanosleep(40);
            prev = g_scanval[b - 1];
        }
        g_scanval[b] = prev + total;
        __threadfence();
        g_scanflag[b] = 1;
        s_prev = prev;
    }
    __syncthreads();
    int base = s_prev;
    if (i < NKEY) { g_off2[i] = excl + base; g_cur2[i] = excl + base; }
    if (b == NB - 1 && t == 0) g_off2[NKEY] = base + total;
}

__global__ void k_scatter(const int* __restrict__ src, const int* __restrict__ dst,
                          const int* __restrict__ et) {
    int e = blockIdx.x * blockDim.x + threadIdx.x;
    if (e < NE) {
        int p = atomicAdd(&g_cur2[dst[e] * 8 + et[e]], 1);
        g_esrc[p] = src[e];
    }
}

// ---------------- aggregation: one warp per (dst,rel) bucket ----------------
__global__ void __launch_bounds__(256) k_agg(int layer) {
    int gid = (blockIdx.x * 256 + threadIdx.x) >> 5;
    int lane = threadIdx.x & 31;
    if (gid >= NKEY) return;
    const uint2* hin = (const uint2*)(layer ? g_h1 : g_hbf);
    int e0 = g_off2[gid], e1 = g_off2[gid + 1];
    float a0 = 0.f, a1 = 0.f, a2 = 0.f, a3 = 0.f;
    for (int e = e0; e < e1; e++) {
        int s = g_esrc[e];
        uint2 raw = hin[(size_t)s * 32 + lane];
        __nv_bfloat162 p0 = *(__nv_bfloat162*)&raw.x;
        __nv_bfloat162 p1 = *(__nv_bfloat162*)&raw.y;
        float2 f0 = __bfloat1622float2(p0);
        float2 f1 = __bfloat1622float2(p1);
        a0 += f0.x; a1 += f0.y; a2 += f1.x; a3 += f1.y;
    }
    __nv_bfloat162 o0 = __floats2bfloat162_rn(a0, a1);
    __nv_bfloat162 o1 = __floats2bfloat162_rn(a2, a3);
    uint2 o; o.x = *(unsigned*)&o0; o.y = *(unsigned*)&o1;
    ((uint2*)g_T)[(size_t)gid * 32 + lane] = o;
}

// ---------------- GEMM: out = relu([T | hin] @ [W | Wself] + b), bf16 wmma, cp.async 2-stage ----
__global__ void __launch_bounds__(512)
k_gemm(const float* __restrict__ bias, int layer) {
    extern __shared__ char smraw[];
    const __nv_bfloat16* hin = layer ? g_h1 : g_hbf;
    const __nv_bfloat16* Wb  = layer ? g_Wb2 : g_Wb1;
    int m0 = blockIdx.x * 128;
    int t = threadIdx.x;
    int warp = t >> 5;
    int wm = warp >> 2;
    int wn = warp & 3;

    wmma::fragment<wmma::accumulator, 16, 16, 16, float> c[2][2];
    #pragma unroll
    for (int i = 0; i < 2; i++)
        #pragma unroll
        for (int j = 0; j < 2; j++) wmma::fill_fragment(c[i][j], 0.f);

    auto load_tiles = [&](int stage, int kb) {
        char* sA = smraw + stage * 2 * TB;
        char* sB = sA + TB;
        #pragma unroll
        for (int i = 0; i < 4; i++) {
            int idx = t + i * 512;
            int row = idx >> 4;
            int ch  = idx & 15;
            int gr = m0 + row;
            int vsz = 16;
            if (gr >= NN) { gr = 0; vsz = 0; }
            const char* src = (kb < 8)
                ? (const char*)(g_T + (size_t)gr * 1024 + kb * 128) + ch * 16
                : (const char*)(hin + (size_t)gr * 128) + ch * 16;
            cp_async16(sA + row * (PAD * 2) + ch * 16, src, vsz);
        }
        #pragma unroll
        for (int i = 0; i < 4; i++) {
            int idx = t + i * 512;
            int row = idx >> 4;
            int ch  = idx & 15;
            const char* src = (const char*)(Wb + (size_t)kb * F * F + row * 128) + ch * 16;
            cp_async16(sB + row * (PAD * 2) + ch * 16, src, 16);
        }
    };

    load_tiles(0, 0);
    CP_COMMIT();

    for (int kb = 0; kb < 9; kb++) {
        if (kb + 1 < 9) {
            load_tiles((kb + 1) & 1, kb + 1);
            CP_COMMIT();
            CP_WAIT(1);
        } else {
            CP_WAIT(0);
        }
        __syncthreads();

        const __nv_bfloat16* sA = (const __nv_bfloat16*)(smraw + (kb & 1) * 2 * TB);
        const __nv_bfloat16* sB = sA + 128 * PAD;
        #pragma unroll
        for (int ks = 0; ks < 8; ks++) {
            wmma::fragment<wmma::matrix_a, 16, 16, 16, __nv_bfloat16, wmma::row_major> af[2];
            wmma::fragment<wmma::matrix_b, 16, 16, 16, __nv_bfloat16, wmma::row_major> bf[2];
            #pragma unroll
            for (int i = 0; i < 2; i++)
                wmma::load_matrix_sync(af[i], sA + (wm * 32 + i * 16) * PAD + ks * 16, PAD);
            #pragma unroll
            for (int j = 0; j < 2; j++)
                wmma::load_matrix_sync(bf[j], sB + (ks * 16) * PAD + wn * 32 + j * 16, PAD);
            #pragma unroll
            for (int i = 0; i < 2; i++)
                #pragma unroll
                for (int j = 0; j < 2; j++)
                    wmma::mma_sync(c[i][j], af[i], bf[j], c[i][j]);
        }
        __syncthreads();
    }

    float* sC = (float*)smraw;
    #pragma unroll
    for (int i = 0; i < 2; i++)
        #pragma unroll
        for (int j = 0; j < 2; j++)
            wmma::store_matrix_sync(sC + (wm * 32 + i * 16) * 132 + wn * 32 + j * 16,
                                    c[i][j], 132, wmma::mem_row_major);
    __syncthreads();

    if (layer == 0) {
        #pragma unroll
        for (int i = 0; i < 8; i++) {
            int idx = t + i * 512;
            int row = idx >> 5;
            int c4  = idx & 31;
            if (m0 + row < NN) {
                float* sp = sC + row * 132 + c4 * 4;
                float x = fmaxf(sp[0] + bias[c4 * 4 + 0], 0.f);
                float y = fmaxf(sp[1] + bias[c4 * 4 + 1], 0.f);
                float z = fmaxf(sp[2] + bias[c4 * 4 + 2], 0.f);
                float w = fmaxf(sp[3] + bias[c4 * 4 + 3], 0.f);
                __nv_bfloat162 p0 = __floats2bfloat162_rn(x, y);
                __nv_bfloat162 p1 = __floats2bfloat162_rn(z, w);
                uint2 o; o.x = *(unsigned*)&p0; o.y = *(unsigned*)&p1;
                ((uint2*)g_h1)[(size_t)(m0 + row) * 32 + c4] = o;
            }
        }
    } else {
        int col = t & 127;
        int rg = t >> 7;
        float bc = bias[col];
        float s = 0.f;
        for (int r = rg * 32; r < rg * 32 + 32; r++) {
            if (m0 + r < NN) s += fmaxf(sC[r * 132 + col] + bc, 0.f);
        }
        atomicAdd(&g_pool[col], s);
    }
}

// ---------------- final ----------------
__global__ void k_final(const float* __restrict__ fc_w, const float* __restrict__ fc_b,
                        float* __restrict__ out) {
    __shared__ float red[F];
    int t = threadIdx.x;
    red[t] = g_pool[t] * (1.f / (float)NN) * fc_w[t];
    __syncthreads();
    for (int o = 64; o > 0; o >>= 1) {
        if (t < o) red[t] += red[t + o];
        __syncthreads();
    }
    if (t == 0) {
        float logit = red[0] + fc_b[0];
        out[0] = 1.f / (1.f + expf(-logit));
    }
}

// ---------------- launch ----------------
extern "C" void kernel_launch(void* const* d_in, const int* in_sizes, int n_in,
                              void* d_out, int out_size) {
    const float* in_feat = (const float*)d_in[0];
    const float* W1   = (const float*)d_in[1];
    const float* W1s  = (const float*)d_in[2];
    const float* b1   = (const float*)d_in[3];
    const float* W2   = (const float*)d_in[4];
    const float* W2s  = (const float*)d_in[5];
    const float* b2   = (const float*)d_in[6];
    const float* fcw  = (const float*)d_in[7];
    const float* fcb  = (const float*)d_in[8];
    const int*   src  = (const int*)d_in[9];
    const int*   dst  = (const int*)d_in[10];
    const int*   et   = (const int*)d_in[11];
    float* out = (float*)d_out;

    cudaFuncSetAttribute(k_gemm, cudaFuncAttributeMaxDynamicSharedMemorySize, GEMM_SMEM);

    const int grid = (NN + 127) / 128;   // 391

    k_setup<<<SETUP_GRID, 256>>>(in_feat, W1, W1s, W2, W2s);          // 1
    k_hist<<<(NE + 255) / 256, 256>>>(dst, et);                       // 2
    k_scan<<<NB, 1024>>>();                                           // 3
    k_scatter<<<(NE + 255) / 256, 256>>>(src, dst, et);               // 4
    k_agg<<<(NKEY + 7) / 8, 256>>>(0);                                // 5
    k_gemm<<<grid, 512, GEMM_SMEM>>>(b1, 0);                          // 6  <- ncu captures this
    k_agg<<<(NKEY + 7) / 8, 256>>>(1);                                // 7
    k_gemm<<<grid, 512, GEMM_SMEM>>>(b2, 1);                          // 8
    k_final<<<1, 128>>>(fcw, fcb, out);                               // 9
}

// round 8
// speedup vs baseline: 2.1274x; 2.1274x over previous
#include <cuda_runtime.h>
#include <cuda_bf16.h>
#include <mma.h>
#include <math.h>
#include <cstdint>

using namespace nvcuda;

// Problem constants
#define NN 50000
#define NE 800000
#define F  128
#define R  8
#define NKEY (NN * R)                // 400000 (dst,rel) buckets
#define NB  ((NKEY + 1023) / 1024)   // 391 scan blocks

// padded row: 144 bf16 = 288 bytes (conflict-free smem stride, contiguous GMEM tiles)
#define PADC 144
#define ROWB (PADC * 2)              // 288 bytes
#define TILEB (128 * ROWB)           // 36864 bytes per 128-row tile
#define NSTAGE 3
#define STAGEB (2 * TILEB)           // A + B per stage = 73728
#define GEMM_SMEM (NSTAGE * STAGEB + 64)   // + mbarriers

// ---------------- device scratch (no cudaMalloc allowed) ----------------
// +128 slack rows so tail-tile bulk copies stay in-bounds (garbage rows are discarded)
__device__ __nv_bfloat16 g_T[((size_t)R * NN + 128) * PADC];  // kb-major: [kb][node][144]
__device__ __nv_bfloat16 g_h1[((size_t)NN + 128) * PADC];     // layer-1 output, padded rows
__device__ __nv_bfloat16 g_hbf[((size_t)NN + 128) * PADC];    // bf16 input copy, padded rows
__device__ __nv_bfloat16 g_Wb1[9 * 128 * PADC];               // W1 blocks (+self), padded rows
__device__ __nv_bfloat16 g_Wb2[9 * 128 * PADC];
__device__ int   g_deg2[NKEY];
__device__ int   g_off2[NKEY + 1];
__device__ int   g_cur2[NKEY];
__device__ int   g_bsum[NB];
__device__ int   g_boff[NB];
__device__ int   g_esrc[NE];
__device__ float g_pool[F];

// ---------------- PTX helpers ----------------
__device__ __forceinline__ void mbar_init(uint32_t mbar, uint32_t cnt) {
    asm volatile("mbarrier.init.shared.b64 [%0], %1;" :: "r"(mbar), "r"(cnt) : "memory");
}
__device__ __forceinline__ void mbar_expect_tx(uint32_t mbar, uint32_t bytes) {
    asm volatile("mbarrier.arrive.expect_tx.shared.b64 _, [%0], %1;"
                 :: "r"(mbar), "r"(bytes) : "memory");
}
__device__ __forceinline__ void mbar_wait(uint32_t mbar, uint32_t parity) {
    asm volatile(
        "{\n\t.reg .pred P;\n\t"
        "W%=:\n\t"
        "mbarrier.try_wait.parity.acquire.cta.shared::cta.b64 P, [%0], %1, 0x989680;\n\t"
        "@!P bra.uni W%=;\n\t}"
        :: "r"(mbar), "r"(parity) : "memory");
}
__device__ __forceinline__ void bulk_g2s(uint32_t sdst, const void* gsrc, uint32_t bytes,
                                         uint32_t mbar) {
    asm volatile(
        "cp.async.bulk.shared::cta.global.mbarrier::complete_tx::bytes [%0], [%1], %2, [%3];"
        :: "r"(sdst), "l"(gsrc), "r"(bytes), "r"(mbar) : "memory");
}

// ---------------- fused setup: zero CSR state + fp32->bf16 converts (padded rows) ----------------
#define NZ_BLK ((NKEY + 255) / 256)
#define NC_BLK ((NN * F / 4 + 255) / 256)
#define NW_ELEM (9 * F * F / 4)
#define NW_BLK ((NW_ELEM + 255) / 256)
#define SETUP_GRID (NZ_BLK + NC_BLK + 2 * NW_BLK)

__global__ void __launch_bounds__(256)
k_setup(const float* __restrict__ in_feat,
        const float* __restrict__ W1, const float* __restrict__ W1s,
        const float* __restrict__ W2, const float* __restrict__ W2s) {
    int b = blockIdx.x;
    int t = threadIdx.x;
    if (b < NZ_BLK) {
        int i = b * 256 + t;
        if (i < NKEY) g_deg2[i] = 0;
        if (i < F)    g_pool[i] = 0.f;
        return;
    }
    b -= NZ_BLK;
    if (b < NC_BLK) {
        int i = b * 256 + t;
        if (i >= NN * F / 4) return;
        float4 v = ((const float4*)in_feat)[i];
        __nv_bfloat162 p0 = __floats2bfloat162_rn(v.x, v.y);
        __nv_bfloat162 p1 = __floats2bfloat162_rn(v.z, v.w);
        uint2 o; o.x = *(unsigned*)&p0; o.y = *(unsigned*)&p1;
        int row = i >> 5, c4 = i & 31;
        ((uint2*)g_hbf)[(size_t)row * 36 + c4] = o;     // 144 bf16 row = 36 uint2
        return;
    }
    b -= NC_BLK;
    int which = (b < NW_BLK) ? 0 : 1;
    if (which) b -= NW_BLK;
    int i = b * 256 + t;
    if (i >= NW_ELEM) return;
    const float* W  = which ? W2  : W1;
    const float* Ws = which ? W2s : W1s;
    const float4* src = (i < 8 * F * F / 4) ? ((const float4*)W + i)
                                            : ((const float4*)Ws + (i - 8 * F * F / 4));
    float4 v = *src;
    __nv_bfloat162 p0 = __floats2bfloat162_rn(v.x, v.y);
    __nv_bfloat162 p1 = __floats2bfloat162_rn(v.z, v.w);
    uint2 o; o.x = *(unsigned*)&p0; o.y = *(unsigned*)&p1;
    int row = i >> 5, c4 = i & 31;                      // row 0..1151 across 9 blocks
    ((uint2*)(which == 0 ? g_Wb1 : g_Wb2))[(size_t)row * 36 + c4] = o;
}

// ---------------- CSR build ----------------
__global__ void k_hist(const int* __restrict__ dst, const int* __restrict__ et) {
    int e = blockIdx.x * blockDim.x + threadIdx.x;
    if (e < NE) atomicAdd(&g_deg2[dst[e] * 8 + et[e]], 1);
}

__global__ void __launch_bounds__(1024) k_scan1() {
    __shared__ int ws[32];
    int b = blockIdx.x, t = threadIdx.x;
    int lane = t & 31, wid = t >> 5;
    int i = b * 1024 + t;
    int v = (i < NKEY) ? g_deg2[i] : 0;
    #pragma unroll
    for (int o = 16; o > 0; o >>= 1) v += __shfl_down_sync(~0u, v, o);
    if (lane == 0) ws[wid] = v;
    __syncthreads();
    if (wid == 0) {
        int s = ws[lane];
        #pragma unroll
        for (int o = 16; o > 0; o >>= 1) s += __shfl_down_sync(~0u, s, o);
        if (lane == 0) g_bsum[b] = s;
    }
}

__global__ void __launch_bounds__(512) k_scan2() {
    __shared__ int ws[16];
    int t = threadIdx.x, lane = t & 31, wid = t >> 5;
    int v = (t < NB) ? g_bsum[t] : 0;
    int x = v;
    #pragma unroll
    for (int o = 1; o < 32; o <<= 1) { int u = __shfl_up_sync(~0u, x, o); if (lane >= o) x += u; }
    if (lane == 31) ws[wid] = x;
    __syncthreads();
    if (wid == 0 && lane < 16) {
        int s = ws[lane];
        #pragma unroll
        for (int o = 1; o < 16; o <<= 1) { int u = __shfl_up_sync(0xffffu, s, o); if (lane >= o) s += u; }
        ws[lane] = s;
    }
    __syncthreads();
    int excl = x - v + (wid > 0 ? ws[wid - 1] : 0);
    if (t < NB) g_boff[t] = excl;
    if (t == NB - 1) g_off2[NKEY] = excl + v;
}

__global__ void __launch_bounds__(1024) k_scan3() {
    __shared__ int ws[32];
    int b = blockIdx.x, t = threadIdx.x;
    int lane = t & 31, wid = t >> 5;
    int i = b * 1024 + t;
    int v = (i < NKEY) ? g_deg2[i] : 0;
    int x = v;
    #pragma unroll
    for (int o = 1; o < 32; o <<= 1) { int u = __shfl_up_sync(~0u, x, o); if (lane >= o) x += u; }
    if (lane == 31) ws[wid] = x;
    __syncthreads();
    if (wid == 0) {
        int s = ws[lane];
        #pragma unroll
        for (int o = 1; o < 32; o <<= 1) { int u = __shfl_up_sync(~0u, s, o); if (lane >= o) s += u; }
        ws[lane] = s;
    }
    __syncthreads();
    int excl = x - v + (wid > 0 ? ws[wid - 1] : 0) + g_boff[b];
    if (i < NKEY) { g_off2[i] = excl; g_cur2[i] = excl; }
}

__global__ void k_scatter(const int* __restrict__ src, const int* __restrict__ dst,
                          const int* __restrict__ et) {
    int e = blockIdx.x * blockDim.x + threadIdx.x;
    if (e < NE) {
        int p = atomicAdd(&g_cur2[dst[e] * 8 + et[e]], 1);
        g_esrc[p] = src[e];
    }
}

// ---------------- aggregation: one warp per (dst,rel) bucket ----------------
// writes g_T kb-major: row = rel*NN + dst (padded 144-col rows)
__global__ void __launch_bounds__(256) k_agg(int layer) {
    int gid = (blockIdx.x * 256 + threadIdx.x) >> 5;
    int lane = threadIdx.x & 31;
    if (gid >= NKEY) return;
    const uint2* hin = (const uint2*)(layer ? g_h1 : g_hbf);
    int e0 = g_off2[gid], e1 = g_off2[gid + 1];
    float a0 = 0.f, a1 = 0.f, a2 = 0.f, a3 = 0.f;
    for (int e = e0; e < e1; e++) {
        int s = g_esrc[e];
        uint2 raw = hin[(size_t)s * 36 + lane];
        __nv_bfloat162 p0 = *(__nv_bfloat162*)&raw.x;
        __nv_bfloat162 p1 = *(__nv_bfloat162*)&raw.y;
        float2 f0 = __bfloat1622float2(p0);
        float2 f1 = __bfloat1622float2(p1);
        a0 += f0.x; a1 += f0.y; a2 += f1.x; a3 += f1.y;
    }
    __nv_bfloat162 o0 = __floats2bfloat162_rn(a0, a1);
    __nv_bfloat162 o1 = __floats2bfloat162_rn(a2, a3);
    uint2 o; o.x = *(unsigned*)&o0; o.y = *(unsigned*)&o1;
    int dstn = gid >> 3, rel = gid & 7;
    ((uint2*)g_T)[((size_t)rel * NN + dstn) * 36 + lane] = o;
}

// ---------------- GEMM: relu([T | hin] @ [W | Wself] + b), bf16 wmma, bulk-copy 3-stage ----
__global__ void __launch_bounds__(512)
k_gemm(const float* __restrict__ bias, int layer) {
    extern __shared__ char smraw[];
    uint32_t sbase = (uint32_t)__cvta_generic_to_shared(smraw);
    const __nv_bfloat16* hin = layer ? g_h1 : g_hbf;
    const __nv_bfloat16* Wb  = layer ? g_Wb2 : g_Wb1;
    int m0 = blockIdx.x * 128;
    int t = threadIdx.x;
    int warp = t >> 5;
    int wm = warp >> 2;
    int wn = warp & 3;
    uint32_t mb0 = sbase + NSTAGE * STAGEB;

    if (t == 0) {
        #pragma unroll
        for (int s = 0; s < NSTAGE; s++) mbar_init(mb0 + 8 * s, 1);
    }
    __syncthreads();

    auto issue = [&](int kb) {
        int s = kb % NSTAGE;
        uint32_t sA = sbase + s * STAGEB;
        uint32_t sB = sA + TILEB;
        uint32_t mb = mb0 + 8 * s;
        mbar_expect_tx(mb, 2 * TILEB);
        const void* srcA = (kb < 8)
            ? (const void*)(g_T + ((size_t)kb * NN + m0) * PADC)
            : (const void*)(hin + (size_t)m0 * PADC);
        bulk_g2s(sA, srcA, TILEB, mb);
        bulk_g2s(sB, (const void*)(Wb + (size_t)kb * 128 * PADC), TILEB, mb);
    };

    wmma::fragment<wmma::accumulator, 16, 16, 16, float> c[2][2];
    #pragma unroll
    for (int i = 0; i < 2; i++)
        #pragma unroll
        for (int j = 0; j < 2; j++) wmma::fill_fragment(c[i][j], 0.f);

    if (t == 0) { issue(0); issue(1); issue(2); }

    for (int kb = 0; kb < 9; kb++) {
        int s = kb % NSTAGE;
        uint32_t par = (kb / NSTAGE) & 1;
        mbar_wait(mb0 + 8 * s, par);

        const __nv_bfloat16* sA = (const __nv_bfloat16*)(smraw + s * STAGEB);
        const __nv_bfloat16* sB = sA + 128 * PADC;
        #pragma unroll
        for (int ks = 0; ks < 8; ks++) {
            wmma::fragment<wmma::matrix_a, 16, 16, 16, __nv_bfloat16, wmma::row_major> af[2];
            wmma::fragment<wmma::matrix_b, 16, 16, 16, __nv_bfloat16, wmma::row_major> bf[2];
            #pragma unroll
            for (int i = 0; i < 2; i++)
                wmma::load_matrix_sync(af[i], sA + (wm * 32 + i * 16) * PADC + ks * 16, PADC);
            #pragma unroll
            for (int j = 0; j < 2; j++)
                wmma::load_matrix_sync(bf[j], sB + (ks * 16) * PADC + wn * 32 + j * 16, PADC);
            #pragma unroll
            for (int i = 0; i < 2; i++)
                #pragma unroll
                for (int j = 0; j < 2; j++)
                    wmma::mma_sync(c[i][j], af[i], bf[j], c[i][j]);
        }
        __syncthreads();                 // all warps done reading stage s
        if (t == 0 && kb + NSTAGE < 9) issue(kb + NSTAGE);
    }

    // epilogue: C -> smem fp32 [128][132] (stage 0 region)
    float* sC = (float*)smraw;
    #pragma unroll
    for (int i = 0; i < 2; i++)
        #pragma unroll
        for (int j = 0; j < 2; j++)
            wmma::store_matrix_sync(sC + (wm * 32 + i * 16) * 132 + wn * 32 + j * 16,
                                    c[i][j], 132, wmma::mem_row_major);
    __syncthreads();

    if (layer == 0) {
        #pragma unroll
        for (int i = 0; i < 8; i++) {
            int idx = t + i * 512;
            int row = idx >> 5;
            int c4  = idx & 31;
            if (m0 + row < NN) {
                float* sp = sC + row * 132 + c4 * 4;
                float x = fmaxf(sp[0] + bias[c4 * 4 + 0], 0.f);
                float y = fmaxf(sp[1] + bias[c4 * 4 + 1], 0.f);
                float z = fmaxf(sp[2] + bias[c4 * 4 + 2], 0.f);
                float w = fmaxf(sp[3] + bias[c4 * 4 + 3], 0.f);
                __nv_bfloat162 p0 = __floats2bfloat162_rn(x, y);
                __nv_bfloat162 p1 = __floats2bfloat162_rn(z, w);
                uint2 o; o.x = *(unsigned*)&p0; o.y = *(unsigned*)&p1;
                ((uint2*)g_h1)[(size_t)(m0 + row) * 36 + c4] = o;
            }
        }
    } else {
        int col = t & 127;
        int rg = t >> 7;
        float bc = bias[col];
        float s = 0.f;
        for (int r = rg * 32; r < rg * 32 + 32; r++) {
            if (m0 + r < NN) s += fmaxf(sC[r * 132 + col] + bc, 0.f);
        }
        atomicAdd(&g_pool[col], s);
    }
}

// ---------------- final ----------------
__global__ void k_final(const float* __restrict__ fc_w, const float* __restrict__ fc_b,
                        float* __restrict__ out) {
    __shared__ float red[F];
    int t = threadIdx.x;
    red[t] = g_pool[t] * (1.f / (float)NN) * fc_w[t];
    __syncthreads();
    for (int o = 64; o > 0; o >>= 1) {
        if (t < o) red[t] += red[t + o];
        __syncthreads();
    }
    if (t == 0) {
        float logit = red[0] + fc_b[0];
        out[0] = 1.f / (1.f + expf(-logit));
    }
}

// ---------------- launch ----------------
extern "C" void kernel_launch(void* const* d_in, const int* in_sizes, int n_in,
                              void* d_out, int out_size) {
    const float* in_feat = (const float*)d_in[0];
    const float* W1   = (const float*)d_in[1];
    const float* W1s  = (const float*)d_in[2];
    const float* b1   = (const float*)d_in[3];
    const float* W2   = (const float*)d_in[4];
    const float* W2s  = (const float*)d_in[5];
    const float* b2   = (const float*)d_in[6];
    const float* fcw  = (const float*)d_in[7];
    const float* fcb  = (const float*)d_in[8];
    const int*   src  = (const int*)d_in[9];
    const int*   dst  = (const int*)d_in[10];
    const int*   et   = (const int*)d_in[11];
    float* out = (float*)d_out;

    cudaFuncSetAttribute(k_gemm, cudaFuncAttributeMaxDynamicSharedMemorySize, GEMM_SMEM);

    const int grid = (NN + 127) / 128;   // 391

    k_setup<<<SETUP_GRID, 256>>>(in_feat, W1, W1s, W2, W2s);
    k_hist<<<(NE + 255) / 256, 256>>>(dst, et);
    k_scan1<<<NB, 1024>>>();
    k_scan2<<<1, 512>>>();
    k_scan3<<<NB, 1024>>>();
    k_scatter<<<(NE + 255) / 256, 256>>>(src, dst, et);
    k_agg<<<(NKEY + 7) / 8, 256>>>(0);
    k_gemm<<<grid, 512, GEMM_SMEM>>>(b1, 0);
    k_agg<<<(NKEY + 7) / 8, 256>>>(1);
    k_gemm<<<grid, 512, GEMM_SMEM>>>(b2, 1);
    k_final<<<1, 128>>>(fcw, fcb, out);
}

// round 9
// speedup vs baseline: 2.5863x; 1.2157x over previous
#include <cuda_runtime.h>
#include <cuda_bf16.h>
#include <mma.h>
#include <math.h>
#include <cstdint>

using namespace nvcuda;

// Problem constants
#define NN 50000
#define NE 800000
#define F  128
#define R  8
#define NKEY (NN * R)                // 400000 (rel,dst) buckets, key = rel*NN + dst
#define NB  ((NKEY + 1023) / 1024)   // 391 scan blocks

// padded row: 144 bf16 = 288 bytes
#define PADC 144
#define ROWB (PADC * 2)              // 288 bytes
#define TILEB (128 * ROWB)           // 36864 bytes per 128-row tile
#define STAGEB (2 * TILEB)           // A + B per stage
#define GEMM_SMEM (2 * STAGEB + 64)  // 2 stages + mbarriers = 147520

// ---------------- device scratch (no cudaMalloc allowed) ----------------
__device__ __nv_bfloat16 g_h1[((size_t)NN + 128) * PADC];     // layer-1 output, padded rows
__device__ __nv_bfloat16 g_hbf[((size_t)NN + 128) * PADC];    // bf16 input copy, padded rows
__device__ __nv_bfloat16 g_Wb1[9 * 128 * PADC];               // W1 blocks (+self), padded rows
__device__ __nv_bfloat16 g_Wb2[9 * 128 * PADC];
__device__ int      g_deg2[NKEY];
__device__ int      g_off2[NKEY + 1];
__device__ int      g_cur2[NKEY];
__device__ int      g_bsum[NB];
__device__ int      g_boff[NB];
__device__ uint32_t g_epack[NE];                              // src | dst<<16, sorted by (rel,dst)
__device__ float    g_pool[F];

// ---------------- PTX helpers ----------------
__device__ __forceinline__ void mbar_init(uint32_t mbar, uint32_t cnt) {
    asm volatile("mbarrier.init.shared.b64 [%0], %1;" :: "r"(mbar), "r"(cnt) : "memory");
}
__device__ __forceinline__ void mbar_arrive(uint32_t mbar) {
    asm volatile("mbarrier.arrive.release.cta.shared::cta.b64 _, [%0];" :: "r"(mbar) : "memory");
}
__device__ __forceinline__ void mbar_arrive_expect_tx(uint32_t mbar, uint32_t bytes) {
    asm volatile("mbarrier.arrive.expect_tx.shared.b64 _, [%0], %1;"
                 :: "r"(mbar), "r"(bytes) : "memory");
}
__device__ __forceinline__ void mbar_wait(uint32_t mbar, uint32_t parity) {
    asm volatile(
        "{\n\t.reg .pred P;\n\t"
        "W%=:\n\t"
        "mbarrier.try_wait.parity.acquire.cta.shared::cta.b64 P, [%0], %1, 0x989680;\n\t"
        "@!P bra.uni W%=;\n\t}"
        :: "r"(mbar), "r"(parity) : "memory");
}
__device__ __forceinline__ void bulk_g2s(uint32_t sdst, const void* gsrc, uint32_t bytes,
                                         uint32_t mbar) {
    asm volatile(
        "cp.async.bulk.shared::cta.global.mbarrier::complete_tx::bytes [%0], [%1], %2, [%3];"
        :: "r"(sdst), "l"(gsrc), "r"(bytes), "r"(mbar) : "memory");
}

// ---------------- fused setup: zero CSR state + fp32->bf16 converts (padded rows) ----------------
#define NZ_BLK ((NKEY + 255) / 256)
#define NC_BLK ((NN * F / 4 + 255) / 256)
#define NW_ELEM (9 * F * F / 4)
#define NW_BLK ((NW_ELEM + 255) / 256)
#define SETUP_GRID (NZ_BLK + NC_BLK + 2 * NW_BLK)

__global__ void __launch_bounds__(256)
k_setup(const float* __restrict__ in_feat,
        const float* __restrict__ W1, const float* __restrict__ W1s,
        const float* __restrict__ W2, const float* __restrict__ W2s) {
    int b = blockIdx.x;
    int t = threadIdx.x;
    if (b < NZ_BLK) {
        int i = b * 256 + t;
        if (i < NKEY) g_deg2[i] = 0;
        if (i < F)    g_pool[i] = 0.f;
        return;
    }
    b -= NZ_BLK;
    if (b < NC_BLK) {
        int i = b * 256 + t;
        if (i >= NN * F / 4) return;
        float4 v = ((const float4*)in_feat)[i];
        __nv_bfloat162 p0 = __floats2bfloat162_rn(v.x, v.y);
        __nv_bfloat162 p1 = __floats2bfloat162_rn(v.z, v.w);
        uint2 o; o.x = *(unsigned*)&p0; o.y = *(unsigned*)&p1;
        int row = i >> 5, c4 = i & 31;
        ((uint2*)g_hbf)[(size_t)row * 36 + c4] = o;
        return;
    }
    b -= NC_BLK;
    int which = (b < NW_BLK) ? 0 : 1;
    if (which) b -= NW_BLK;
    int i = b * 256 + t;
    if (i >= NW_ELEM) return;
    const float* W  = which ? W2  : W1;
    const float* Ws = which ? W2s : W1s;
    const float4* src = (i < 8 * F * F / 4) ? ((const float4*)W + i)
                                            : ((const float4*)Ws + (i - 8 * F * F / 4));
    float4 v = *src;
    __nv_bfloat162 p0 = __floats2bfloat162_rn(v.x, v.y);
    __nv_bfloat162 p1 = __floats2bfloat162_rn(v.z, v.w);
    uint2 o; o.x = *(unsigned*)&p0; o.y = *(unsigned*)&p1;
    int row = i >> 5, c4 = i & 31;
    ((uint2*)(which == 0 ? g_Wb1 : g_Wb2))[(size_t)row * 36 + c4] = o;
}

// ---------------- CSR build: key = rel*NN + dst ----------------
__global__ void k_hist(const int* __restrict__ dst, const int* __restrict__ et) {
    int e = blockIdx.x * blockDim.x + threadIdx.x;
    if (e < NE) atomicAdd(&g_deg2[et[e] * NN + dst[e]], 1);
}

__global__ void __launch_bounds__(1024) k_scan1() {
    __shared__ int ws[32];
    int b = blockIdx.x, t = threadIdx.x;
    int lane = t & 31, wid = t >> 5;
    int i = b * 1024 + t;
    int v = (i < NKEY) ? g_deg2[i] : 0;
    #pragma unroll
    for (int o = 16; o > 0; o >>= 1) v += __shfl_down_sync(~0u, v, o);
    if (lane == 0) ws[wid] = v;
    __syncthreads();
    if (wid == 0) {
        int s = ws[lane];
        #pragma unroll
        for (int o = 16; o > 0; o >>= 1) s += __shfl_down_sync(~0u, s, o);
        if (lane == 0) g_bsum[b] = s;
    }
}

__global__ void __launch_bounds__(512) k_scan2() {
    __shared__ int ws[16];
    int t = threadIdx.x, lane = t & 31, wid = t >> 5;
    int v = (t < NB) ? g_bsum[t] : 0;
    int x = v;
    #pragma unroll
    for (int o = 1; o < 32; o <<= 1) { int u = __shfl_up_sync(~0u, x, o); if (lane >= o) x += u; }
    if (lane == 31) ws[wid] = x;
    __syncthreads();
    if (wid == 0 && lane < 16) {
        int s = ws[lane];
        #pragma unroll
        for (int o = 1; o < 16; o <<= 1) { int u = __shfl_up_sync(0xffffu, s, o); if (lane >= o) s += u; }
        ws[lane] = s;
    }
    __syncthreads();
    int excl = x - v + (wid > 0 ? ws[wid - 1] : 0);
    if (t < NB) g_boff[t] = excl;
    if (t == NB - 1) g_off2[NKEY] = excl + v;
}

__global__ void __launch_bounds__(1024) k_scan3() {
    __shared__ int ws[32];
    int b = blockIdx.x, t = threadIdx.x;
    int lane = t & 31, wid = t >> 5;
    int i = b * 1024 + t;
    int v = (i < NKEY) ? g_deg2[i] : 0;
    int x = v;
    #pragma unroll
    for (int o = 1; o < 32; o <<= 1) { int u = __shfl_up_sync(~0u, x, o); if (lane >= o) x += u; }
    if (lane == 31) ws[wid] = x;
    __syncthreads();
    if (wid == 0) {
        int s = ws[lane];
        #pragma unroll
        for (int o = 1; o < 32; o <<= 1) { int u = __shfl_up_sync(~0u, s, o); if (lane >= o) s += u; }
        ws[lane] = s;
    }
    __syncthreads();
    int excl = x - v + (wid > 0 ? ws[wid - 1] : 0) + g_boff[b];
    if (i < NKEY) { g_off2[i] = excl; g_cur2[i] = excl; }
}

__global__ void k_scatter(const int* __restrict__ src, const int* __restrict__ dst,
                          const int* __restrict__ et) {
    int e = blockIdx.x * blockDim.x + threadIdx.x;
    if (e < NE) {
        int d = dst[e];
        int p = atomicAdd(&g_cur2[et[e] * NN + d], 1);
        g_epack[p] = (uint32_t)src[e] | ((uint32_t)d << 16);
    }
}

// ---------------- fused gather + GEMM + epilogue (warp-specialized) ----------------
// 512 threads: warps 0-7 consumers (wmma), warps 8-15 producers (gather).
// 2 stages (A+B each). Stage kb<8: producers gather rel-kb sums into sA; t256 bulk-copies B.
// Stage kb==8: t256 bulk-copies A (self rows) + B.
__global__ void __launch_bounds__(512)
k_fused(const float* __restrict__ bias, int layer) {
    extern __shared__ char smraw[];
    uint32_t sbase = (uint32_t)__cvta_generic_to_shared(smraw);
    const __nv_bfloat16* hinp = layer ? g_h1 : g_hbf;
    const uint2* hin4 = (const uint2*)hinp;
    const __nv_bfloat16* Wb = layer ? g_Wb2 : g_Wb1;
    int m0 = blockIdx.x * 128;
    int t = threadIdx.x;
    int warp = t >> 5, lane = t & 31;
    uint32_t mbF0 = sbase + 2 * STAGEB;        // full[0], full[1]
    uint32_t mbE0 = mbF0 + 16;                 // empty[0], empty[1]

    if (t == 0) {
        mbar_init(mbF0, 257);     mbar_init(mbF0 + 8, 257);
        mbar_init(mbE0, 256);     mbar_init(mbE0 + 8, 256);
    }
    __syncthreads();

    if (warp < 8) {
        // ---------------- consumer ----------------
        int wm = warp >> 2;      // 0..1 (64-row tiles)
        int wn = warp & 3;       // 0..3 (32-col tiles)
        wmma::fragment<wmma::accumulator, 16, 16, 16, float> c[4][2];
        #pragma unroll
        for (int i = 0; i < 4; i++)
            #pragma unroll
            for (int j = 0; j < 2; j++) wmma::fill_fragment(c[i][j], 0.f);

        for (int kb = 0; kb < 9; kb++) {
            int s = kb & 1;
            uint32_t par = (kb >> 1) & 1;
            mbar_wait(mbF0 + 8 * s, par);
            const __nv_bfloat16* sA = (const __nv_bfloat16*)(smraw + s * STAGEB);
            const __nv_bfloat16* sB = sA + 128 * PADC;
            #pragma unroll
            for (int ks = 0; ks < 8; ks++) {
                wmma::fragment<wmma::matrix_b, 16, 16, 16, __nv_bfloat16, wmma::row_major> bf[2];
                #pragma unroll
                for (int j = 0; j < 2; j++)
                    wmma::load_matrix_sync(bf[j], sB + (ks * 16) * PADC + wn * 32 + j * 16, PADC);
                #pragma unroll
                for (int i = 0; i < 4; i++) {
                    wmma::fragment<wmma::matrix_a, 16, 16, 16, __nv_bfloat16, wmma::row_major> af;
                    wmma::load_matrix_sync(af, sA + (wm * 64 + i * 16) * PADC + ks * 16, PADC);
                    #pragma unroll
                    for (int j = 0; j < 2; j++)
                        wmma::mma_sync(c[i][j], af, bf[j], c[i][j]);
                }
            }
            mbar_arrive(mbE0 + 8 * s);
        }
        __syncthreads();
        // dump C -> smem fp32 [128][132]
        float* sC = (float*)smraw;
        #pragma unroll
        for (int i = 0; i < 4; i++)
            #pragma unroll
            for (int j = 0; j < 2; j++)
                wmma::store_matrix_sync(sC + (wm * 64 + i * 16) * 132 + wn * 32 + j * 16,
                                        c[i][j], 132, wmma::mem_row_major);
    } else {
        // ---------------- producer ----------------
        int pw = warp - 8;                     // 0..7, owns rows pw*16..pw*16+15
        int nn = NN - m0; if (nn > 128) nn = 128;
        for (int kb = 0; kb < 9; kb++) {
            int s = kb & 1;
            uint32_t par = ((kb >> 1) & 1) ^ 1;
            mbar_wait(mbE0 + 8 * s, par);
            uint32_t mbF = mbF0 + 8 * s;
            char* sAp = smraw + s * STAGEB;
            if (t == 256) {
                if (kb < 8) {
                    mbar_arrive_expect_tx(mbF, TILEB);
                    bulk_g2s(sbase + s * STAGEB + TILEB,
                             (const void*)(Wb + (size_t)kb * 128 * PADC), TILEB, mbF);
                } else {
                    mbar_arrive_expect_tx(mbF, 2 * TILEB);
                    bulk_g2s(sbase + s * STAGEB,
                             (const void*)(hinp + (size_t)m0 * PADC), TILEB, mbF);
                    bulk_g2s(sbase + s * STAGEB + TILEB,
                             (const void*)(Wb + (size_t)8 * 128 * PADC), TILEB, mbF);
                }
            }
            if (kb < 8) {
                // zero my 16 rows (lane's 8-byte slot)
                #pragma unroll
                for (int r = 0; r < 16; r++)
                    *(uint2*)(sAp + (pw * 16 + r) * ROWB + lane * 8) = make_uint2(0u, 0u);
                int nbeg = pw * 16;
                int nend = nbeg + 16; if (nend > nn) nend = nn;
                if (nbeg < nend) {
                    int wb = g_off2[kb * NN + m0 + nbeg];
                    int we = g_off2[kb * NN + m0 + nend];
                    int cur = -1;
                    float a0 = 0.f, a1 = 0.f, a2 = 0.f, a3 = 0.f;
                    for (int e = wb; e < we; e += 32) {
                        uint32_t pk = 0xFFFF0000u;               // sentinel dst
                        if (e + lane < we) pk = g_epack[e + lane];
                        int ccnt = we - e; if (ccnt > 32) ccnt = 32;
                        for (int g = 0; g < ccnt; g += 8) {
                            uint2 rr[8]; int dd[8];
                            #pragma unroll
                            for (int j = 0; j < 8; j++) {
                                uint32_t p = __shfl_sync(0xffffffffu, pk, g + j);
                                dd[j] = (int)(p >> 16);
                                rr[j] = hin4[(size_t)(p & 0xFFFFu) * 36 + lane];
                            }
                            #pragma unroll
                            for (int j = 0; j < 8; j++) {
                                if (dd[j] == 0xFFFF) continue;
                                if (dd[j] != cur) {
                                    if (cur >= 0) {
                                        __nv_bfloat162 o0 = __floats2bfloat162_rn(a0, a1);
                                        __nv_bfloat162 o1 = __floats2bfloat162_rn(a2, a3);
                                        *(uint2*)(sAp + (cur - m0) * ROWB + lane * 8) =
                                            make_uint2(*(unsigned*)&o0, *(unsigned*)&o1);
                                    }
                                    cur = dd[j];
                                    a0 = a1 = a2 = a3 = 0.f;
                                }
                                __nv_bfloat162 p0 = *(__nv_bfloat162*)&rr[j].x;
                                __nv_bfloat162 p1 = *(__nv_bfloat162*)&rr[j].y;
                                float2 f0 = __bfloat1622float2(p0);
                                float2 f1 = __bfloat1622float2(p1);
                                a0 += f0.x; a1 += f0.y; a2 += f1.x; a3 += f1.y;
                            }
                        }
                    }
                    if (cur >= 0) {
                        __nv_bfloat162 o0 = __floats2bfloat162_rn(a0, a1);
                        __nv_bfloat162 o1 = __floats2bfloat162_rn(a2, a3);
                        *(uint2*)(sAp + (cur - m0) * ROWB + lane * 8) =
                            make_uint2(*(unsigned*)&o0, *(unsigned*)&o1);
                    }
                }
            }
            mbar_arrive(mbF);
        }
        __syncthreads();
    }
    __syncthreads();

    // ---------------- epilogue (all 512 threads) ----------------
    float* sC = (float*)smraw;
    if (layer == 0) {
        #pragma unroll
        for (int i = 0; i < 8; i++) {
            int idx = t + i * 512;
            int row = idx >> 5;
            int c4  = idx & 31;
            if (m0 + row < NN) {
                float* sp = sC + row * 132 + c4 * 4;
                float x = fmaxf(sp[0] + bias[c4 * 4 + 0], 0.f);
                float y = fmaxf(sp[1] + bias[c4 * 4 + 1], 0.f);
                float z = fmaxf(sp[2] + bias[c4 * 4 + 2], 0.f);
                float w = fmaxf(sp[3] + bias[c4 * 4 + 3], 0.f);
                __nv_bfloat162 p0 = __floats2bfloat162_rn(x, y);
                __nv_bfloat162 p1 = __floats2bfloat162_rn(z, w);
                uint2 o; o.x = *(unsigned*)&p0; o.y = *(unsigned*)&p1;
                ((uint2*)g_h1)[(size_t)(m0 + row) * 36 + c4] = o;
            }
        }
    } else {
        int col = t & 127;
        int rg = t >> 7;
        float bc = bias[col];
        float s = 0.f;
        for (int r = rg * 32; r < rg * 32 + 32; r++) {
            if (m0 + r < NN) s += fmaxf(sC[r * 132 + col] + bc, 0.f);
        }
        atomicAdd(&g_pool[col], s);
    }
}

// ---------------- final ----------------
__global__ void k_final(const float* __restrict__ fc_w, const float* __restrict__ fc_b,
                        float* __restrict__ out) {
    __shared__ float red[F];
    int t = threadIdx.x;
    red[t] = g_pool[t] * (1.f / (float)NN) * fc_w[t];
    __syncthreads();
    for (int o = 64; o > 0; o >>= 1) {
        if (t < o) red[t] += red[t + o];
        __syncthreads();
    }
    if (t == 0) {
        float logit = red[0] + fc_b[0];
        out[0] = 1.f / (1.f + expf(-logit));
    }
}

// ---------------- launch ----------------
extern "C" void kernel_launch(void* const* d_in, const int* in_sizes, int n_in,
                              void* d_out, int out_size) {
    const float* in_feat = (const float*)d_in[0];
    const float* W1   = (const float*)d_in[1];
    const float* W1s  = (const float*)d_in[2];
    const float* b1   = (const float*)d_in[3];
    const float* W2   = (const float*)d_in[4];
    const float* W2s  = (const float*)d_in[5];
    const float* b2   = (const float*)d_in[6];
    const float* fcw  = (const float*)d_in[7];
    const float* fcb  = (const float*)d_in[8];
    const int*   src  = (const int*)d_in[9];
    const int*   dst  = (const int*)d_in[10];
    const int*   et   = (const int*)d_in[11];
    float* out = (float*)d_out;

    cudaFuncSetAttribute(k_fused, cudaFuncAttributeMaxDynamicSharedMemorySize, GEMM_SMEM);

    const int grid = (NN + 127) / 128;   // 391

    k_setup<<<SETUP_GRID, 256>>>(in_feat, W1, W1s, W2, W2s);
    k_hist<<<(NE + 255) / 256, 256>>>(dst, et);
    k_scan1<<<NB, 1024>>>();
    k_scan2<<<1, 512>>>();
    k_scan3<<<NB, 1024>>>();
    k_scatter<<<(NE + 255) / 256, 256>>>(src, dst, et);
    k_fused<<<grid, 512, GEMM_SMEM>>>(b1, 0);
    k_fused<<<grid, 512, GEMM_SMEM>>>(b2, 1);
    k_final<<<1, 128>>>(fcw, fcb, out);
}

// round 10
// speedup vs baseline: 2.6405x; 1.0210x over previous
#include <cuda_runtime.h>
#include <cuda_bf16.h>
#include <mma.h>
#include <math.h>
#include <cstdint>

using namespace nvcuda;

// Problem constants
#define NN 50000
#define NE 800000
#define F  128
#define R  8
#define NKEY (NN * R)                // 400000 (rel,dst) buckets, key = rel*NN + dst
#define NB  ((NKEY + 1023) / 1024)   // 391 scan blocks

// padded row: 136 bf16 = 272 bytes -> LDSM rows hit banks 4r mod 32 (conflict-free)
#define PADC 136
#define ROW2 34                      // uint2 per row
#define ROWB (PADC * 2)              // 272 bytes
#define TILEB (128 * ROWB)           // 34816 bytes per 128-row tile
#define STAGEB (2 * TILEB)           // A + B per stage = 69632
#define GEMM_SMEM (2 * STAGEB + 64)  // 2 stages + mbarriers = 139328

// ---------------- device scratch (no cudaMalloc allowed) ----------------
__device__ __nv_bfloat16 g_h1[((size_t)NN + 128) * PADC];     // layer-1 output, padded rows
__device__ __nv_bfloat16 g_hbf[((size_t)NN + 128) * PADC];    // bf16 input copy, padded rows
__device__ __nv_bfloat16 g_Wb1[9 * 128 * PADC];               // W1 blocks (+self), padded rows
__device__ __nv_bfloat16 g_Wb2[9 * 128 * PADC];
__device__ int      g_deg2[NKEY];
__device__ int      g_off2[NKEY + 1];
__device__ int      g_cur2[NKEY];
__device__ int      g_bsum[NB];
__device__ int      g_boff[NB];
__device__ uint32_t g_epack[NE];                              // src | dst<<16, sorted by (rel,dst)
__device__ float    g_pool[F];

// ---------------- PTX helpers ----------------
__device__ __forceinline__ void mbar_init(uint32_t mbar, uint32_t cnt) {
    asm volatile("mbarrier.init.shared.b64 [%0], %1;" :: "r"(mbar), "r"(cnt) : "memory");
}
__device__ __forceinline__ void mbar_arrive(uint32_t mbar) {
    asm volatile("mbarrier.arrive.release.cta.shared::cta.b64 _, [%0];" :: "r"(mbar) : "memory");
}
__device__ __forceinline__ void mbar_arrive_expect_tx(uint32_t mbar, uint32_t bytes) {
    asm volatile("mbarrier.arrive.expect_tx.shared.b64 _, [%0], %1;"
                 :: "r"(mbar), "r"(bytes) : "memory");
}
__device__ __forceinline__ void mbar_wait(uint32_t mbar, uint32_t parity) {
    asm volatile(
        "{\n\t.reg .pred P;\n\t"
        "W%=:\n\t"
        "mbarrier.try_wait.parity.acquire.cta.shared::cta.b64 P, [%0], %1, 0x989680;\n\t"
        "@!P bra.uni W%=;\n\t}"
        :: "r"(mbar), "r"(parity) : "memory");
}
__device__ __forceinline__ void bulk_g2s(uint32_t sdst, const void* gsrc, uint32_t bytes,
                                         uint32_t mbar) {
    asm volatile(
        "cp.async.bulk.shared::cta.global.mbarrier::complete_tx::bytes [%0], [%1], %2, [%3];"
        :: "r"(sdst), "l"(gsrc), "r"(bytes), "r"(mbar) : "memory");
}

// ---------------- fused setup: zero CSR state + fp32->bf16 converts (padded rows) ----------------
#define NZ_BLK ((NKEY + 255) / 256)
#define NC_BLK ((NN * F / 4 + 255) / 256)
#define NW_ELEM (9 * F * F / 4)
#define NW_BLK ((NW_ELEM + 255) / 256)
#define SETUP_GRID (NZ_BLK + NC_BLK + 2 * NW_BLK)

__global__ void __launch_bounds__(256)
k_setup(const float* __restrict__ in_feat,
        const float* __restrict__ W1, const float* __restrict__ W1s,
        const float* __restrict__ W2, const float* __restrict__ W2s) {
    int b = blockIdx.x;
    int t = threadIdx.x;
    if (b < NZ_BLK) {
        int i = b * 256 + t;
        if (i < NKEY) g_deg2[i] = 0;
        if (i < F)    g_pool[i] = 0.f;
        return;
    }
    b -= NZ_BLK;
    if (b < NC_BLK) {
        int i = b * 256 + t;
        if (i >= NN * F / 4) return;
        float4 v = ((const float4*)in_feat)[i];
        __nv_bfloat162 p0 = __floats2bfloat162_rn(v.x, v.y);
        __nv_bfloat162 p1 = __floats2bfloat162_rn(v.z, v.w);
        uint2 o; o.x = *(unsigned*)&p0; o.y = *(unsigned*)&p1;
        int row = i >> 5, c4 = i & 31;
        ((uint2*)g_hbf)[(size_t)row * ROW2 + c4] = o;
        return;
    }
    b -= NC_BLK;
    int which = (b < NW_BLK) ? 0 : 1;
    if (which) b -= NW_BLK;
    int i = b * 256 + t;
    if (i >= NW_ELEM) return;
    const float* W  = which ? W2  : W1;
    const float* Ws = which ? W2s : W1s;
    const float4* src = (i < 8 * F * F / 4) ? ((const float4*)W + i)
                                            : ((const float4*)Ws + (i - 8 * F * F / 4));
    float4 v = *src;
    __nv_bfloat162 p0 = __floats2bfloat162_rn(v.x, v.y);
    __nv_bfloat162 p1 = __floats2bfloat162_rn(v.z, v.w);
    uint2 o; o.x = *(unsigned*)&p0; o.y = *(unsigned*)&p1;
    int row = i >> 5, c4 = i & 31;
    ((uint2*)(which == 0 ? g_Wb1 : g_Wb2))[(size_t)row * ROW2 + c4] = o;
}

// ---------------- CSR build: key = rel*NN + dst ----------------
__global__ void k_hist(const int* __restrict__ dst, const int* __restrict__ et) {
    int e = blockIdx.x * blockDim.x + threadIdx.x;
    if (e < NE) atomicAdd(&g_deg2[et[e] * NN + dst[e]], 1);
}

__global__ void __launch_bounds__(1024) k_scan1() {
    __shared__ int ws[32];
    int b = blockIdx.x, t = threadIdx.x;
    int lane = t & 31, wid = t >> 5;
    int i = b * 1024 + t;
    int v = (i < NKEY) ? g_deg2[i] : 0;
    #pragma unroll
    for (int o = 16; o > 0; o >>= 1) v += __shfl_down_sync(~0u, v, o);
    if (lane == 0) ws[wid] = v;
    __syncthreads();
    if (wid == 0) {
        int s = ws[lane];
        #pragma unroll
        for (int o = 16; o > 0; o >>= 1) s += __shfl_down_sync(~0u, s, o);
        if (lane == 0) g_bsum[b] = s;
    }
}

__global__ void __launch_bounds__(512) k_scan2() {
    __shared__ int ws[16];
    int t = threadIdx.x, lane = t & 31, wid = t >> 5;
    int v = (t < NB) ? g_bsum[t] : 0;
    int x = v;
    #pragma unroll
    for (int o = 1; o < 32; o <<= 1) { int u = __shfl_up_sync(~0u, x, o); if (lane >= o) x += u; }
    if (lane == 31) ws[wid] = x;
    __syncthreads();
    if (wid == 0 && lane < 16) {
        int s = ws[lane];
        #pragma unroll
        for (int o = 1; o < 16; o <<= 1) { int u = __shfl_up_sync(0xffffu, s, o); if (lane >= o) s += u; }
        ws[lane] = s;
    }
    __syncthreads();
    int excl = x - v + (wid > 0 ? ws[wid - 1] : 0);
    if (t < NB) g_boff[t] = excl;
    if (t == NB - 1) g_off2[NKEY] = excl + v;
}

__global__ void __launch_bounds__(1024) k_scan3() {
    __shared__ int ws[32];
    int b = blockIdx.x, t = threadIdx.x;
    int lane = t & 31, wid = t >> 5;
    int i = b * 1024 + t;
    int v = (i < NKEY) ? g_deg2[i] : 0;
    int x = v;
    #pragma unroll
    for (int o = 1; o < 32; o <<= 1) { int u = __shfl_up_sync(~0u, x, o); if (lane >= o) x += u; }
    if (lane == 31) ws[wid] = x;
    __syncthreads();
    if (wid == 0) {
        int s = ws[lane];
        #pragma unroll
        for (int o = 1; o < 32; o <<= 1) { int u = __shfl_up_sync(~0u, s, o); if (lane >= o) s += u; }
        ws[lane] = s;
    }
    __syncthreads();
    int excl = x - v + (wid > 0 ? ws[wid - 1] : 0) + g_boff[b];
    if (i < NKEY) { g_off2[i] = excl; g_cur2[i] = excl; }
}

__global__ void k_scatter(const int* __restrict__ src, const int* __restrict__ dst,
                          const int* __restrict__ et) {
    int e = blockIdx.x * blockDim.x + threadIdx.x;
    if (e < NE) {
        int d = dst[e];
        int p = atomicAdd(&g_cur2[et[e] * NN + d], 1);
        g_epack[p] = (uint32_t)src[e] | ((uint32_t)d << 16);
    }
}

// ---------------- fused gather + GEMM + epilogue (warp-specialized) ----------------
// 512 threads: warps 0-7 consumers (wmma), warps 8-15 producers (gather).
__global__ void __launch_bounds__(512)
k_fused(const float* __restrict__ bias, int layer) {
    extern __shared__ char smraw[];
    uint32_t sbase = (uint32_t)__cvta_generic_to_shared(smraw);
    const __nv_bfloat16* hinp = layer ? g_h1 : g_hbf;
    const uint2* hin4 = (const uint2*)hinp;
    const __nv_bfloat16* Wb = layer ? g_Wb2 : g_Wb1;
    int m0 = blockIdx.x * 128;
    int t = threadIdx.x;
    int warp = t >> 5, lane = t & 31;
    uint32_t mbF0 = sbase + 2 * STAGEB;        // full[0], full[1]
    uint32_t mbE0 = mbF0 + 16;                 // empty[0], empty[1]

    if (t == 0) {
        mbar_init(mbF0, 257);     mbar_init(mbF0 + 8, 257);
        mbar_init(mbE0, 256);     mbar_init(mbE0 + 8, 256);
    }
    __syncthreads();

    if (warp < 8) {
        // ---------------- consumer ----------------
        int wm = warp >> 2;      // 0..1 (64-row tiles)
        int wn = warp & 3;       // 0..3 (32-col tiles)
        wmma::fragment<wmma::accumulator, 16, 16, 16, float> c[4][2];
        #pragma unroll
        for (int i = 0; i < 4; i++)
            #pragma unroll
            for (int j = 0; j < 2; j++) wmma::fill_fragment(c[i][j], 0.f);

        for (int kb = 0; kb < 9; kb++) {
            int s = kb & 1;
            uint32_t par = (kb >> 1) & 1;
            mbar_wait(mbF0 + 8 * s, par);
            const __nv_bfloat16* sA = (const __nv_bfloat16*)(smraw + s * STAGEB);
            const __nv_bfloat16* sB = sA + 128 * PADC;
            #pragma unroll
            for (int ks = 0; ks < 8; ks++) {
                wmma::fragment<wmma::matrix_b, 16, 16, 16, __nv_bfloat16, wmma::row_major> bf[2];
                #pragma unroll
                for (int j = 0; j < 2; j++)
                    wmma::load_matrix_sync(bf[j], sB + (ks * 16) * PADC + wn * 32 + j * 16, PADC);
                #pragma unroll
                for (int i = 0; i < 4; i++) {
                    wmma::fragment<wmma::matrix_a, 16, 16, 16, __nv_bfloat16, wmma::row_major> af;
                    wmma::load_matrix_sync(af, sA + (wm * 64 + i * 16) * PADC + ks * 16, PADC);
                    #pragma unroll
                    for (int j = 0; j < 2; j++)
                        wmma::mma_sync(c[i][j], af, bf[j], c[i][j]);
                }
            }
            mbar_arrive(mbE0 + 8 * s);
        }
        __syncthreads();
        // dump C -> smem fp32 [128][132]
        float* sC = (float*)smraw;
        #pragma unroll
        for (int i = 0; i < 4; i++)
            #pragma unroll
            for (int j = 0; j < 2; j++)
                wmma::store_matrix_sync(sC + (wm * 64 + i * 16) * 132 + wn * 32 + j * 16,
                                        c[i][j], 132, wmma::mem_row_major);
    } else {
        // ---------------- producer ----------------
        int pw = warp - 8;                     // 0..7, owns rows pw*16..pw*16+15
        int nn = NN - m0; if (nn > 128) nn = 128;
        for (int kb = 0; kb < 9; kb++) {
            int s = kb & 1;
            uint32_t par = ((kb >> 1) & 1) ^ 1;
            mbar_wait(mbE0 + 8 * s, par);
            uint32_t mbF = mbF0 + 8 * s;
            char* sAp = smraw + s * STAGEB;
            if (t == 256) {
                if (kb < 8) {
                    mbar_arrive_expect_tx(mbF, TILEB);
                    bulk_g2s(sbase + s * STAGEB + TILEB,
                             (const void*)(Wb + (size_t)kb * 128 * PADC), TILEB, mbF);
                } else {
                    mbar_arrive_expect_tx(mbF, 2 * TILEB);
                    bulk_g2s(sbase + s * STAGEB,
                             (const void*)(hinp + (size_t)m0 * PADC), TILEB, mbF);
                    bulk_g2s(sbase + s * STAGEB + TILEB,
                             (const void*)(Wb + (size_t)8 * 128 * PADC), TILEB, mbF);
                }
            }
            if (kb < 8) {
                // zero my 16 rows (lane's 8-byte slot)
                #pragma unroll
                for (int r = 0; r < 16; r++)
                    *(uint2*)(sAp + (pw * 16 + r) * ROWB + lane * 8) = make_uint2(0u, 0u);
                int nbeg = pw * 16;
                int nend = nbeg + 16; if (nend > nn) nend = nn;
                if (nbeg < nend) {
                    int wb = g_off2[kb * NN + m0 + nbeg];
                    int we = g_off2[kb * NN + m0 + nend];
                    int cur = -1;
                    float a0 = 0.f, a1 = 0.f, a2 = 0.f, a3 = 0.f;
                    for (int e = wb; e < we; e += 32) {
                        uint32_t pk = 0xFFFF0000u;               // sentinel dst
                        if (e + lane < we) pk = g_epack[e + lane];
                        int ccnt = we - e; if (ccnt > 32) ccnt = 32;
                        for (int g = 0; g < ccnt; g += 8) {
                            uint2 rr[8]; int dd[8];
                            #pragma unroll
                            for (int j = 0; j < 8; j++) {
                                uint32_t p = __shfl_sync(0xffffffffu, pk, g + j);
                                dd[j] = (int)(p >> 16);
                                rr[j] = hin4[(size_t)(p & 0xFFFFu) * ROW2 + lane];
                            }
                            #pragma unroll
                            for (int j = 0; j < 8; j++) {
                                if (dd[j] == 0xFFFF) continue;
                                if (dd[j] != cur) {
                                    if (cur >= 0) {
                                        __nv_bfloat162 o0 = __floats2bfloat162_rn(a0, a1);
                                        __nv_bfloat162 o1 = __floats2bfloat162_rn(a2, a3);
                                        *(uint2*)(sAp + (cur - m0) * ROWB + lane * 8) =
                                            make_uint2(*(unsigned*)&o0, *(unsigned*)&o1);
                                    }
                                    cur = dd[j];
                                    a0 = a1 = a2 = a3 = 0.f;
                                }
                                __nv_bfloat162 p0 = *(__nv_bfloat162*)&rr[j].x;
                                __nv_bfloat162 p1 = *(__nv_bfloat162*)&rr[j].y;
                                float2 f0 = __bfloat1622float2(p0);
                                float2 f1 = __bfloat1622float2(p1);
                                a0 += f0.x; a1 += f0.y; a2 += f1.x; a3 += f1.y;
                            }
                        }
                    }
                    if (cur >= 0) {
                        __nv_bfloat162 o0 = __floats2bfloat162_rn(a0, a1);
                        __nv_bfloat162 o1 = __floats2bfloat162_rn(a2, a3);
                        *(uint2*)(sAp + (cur - m0) * ROWB + lane * 8) =
                            make_uint2(*(unsigned*)&o0, *(unsigned*)&o1);
                    }
                }
            }
            mbar_arrive(mbF);
        }
        __syncthreads();
    }
    __syncthreads();

    // ---------------- epilogue (all 512 threads) ----------------
    float* sC = (float*)smraw;
    if (layer == 0) {
        #pragma unroll
        for (int i = 0; i < 8; i++) {
            int idx = t + i * 512;
            int row = idx >> 5;
            int c4  = idx & 31;
            if (m0 + row < NN) {
                float* sp = sC + row * 132 + c4 * 4;
                float x = fmaxf(sp[0] + bias[c4 * 4 + 0], 0.f);
                float y = fmaxf(sp[1] + bias[c4 * 4 + 1], 0.f);
                float z = fmaxf(sp[2] + bias[c4 * 4 + 2], 0.f);
                float w = fmaxf(sp[3] + bias[c4 * 4 + 3], 0.f);
                __nv_bfloat162 p0 = __floats2bfloat162_rn(x, y);
                __nv_bfloat162 p1 = __floats2bfloat162_rn(z, w);
                uint2 o; o.x = *(unsigned*)&p0; o.y = *(unsigned*)&p1;
                ((uint2*)g_h1)[(size_t)(m0 + row) * ROW2 + c4] = o;
            }
        }
    } else {
        int col = t & 127;
        int rg = t >> 7;
        float bc = bias[col];
        float s = 0.f;
        for (int r = rg * 32; r < rg * 32 + 32; r++) {
            if (m0 + r < NN) s += fmaxf(sC[r * 132 + col] + bc, 0.f);
        }
        atomicAdd(&g_pool[col], s);
    }
}

// ---------------- final ----------------
__global__ void k_final(const float* __restrict__ fc_w, const float* __restrict__ fc_b,
                        float* __restrict__ out) {
    __shared__ float red[F];
    int t = threadIdx.x;
    red[t] = g_pool[t] * (1.f / (float)NN) * fc_w[t];
    __syncthreads();
    for (int o = 64; o > 0; o >>= 1) {
        if (t < o) red[t] += red[t + o];
        __syncthreads();
    }
    if (t == 0) {
        float logit = red[0] + fc_b[0];
        out[0] = 1.f / (1.f + expf(-logit));
    }
}

// ---------------- launch ----------------
extern "C" void kernel_launch(void* const* d_in, const int* in_sizes, int n_in,
                              void* d_out, int out_size) {
    const float* in_feat = (const float*)d_in[0];
    const float* W1   = (const float*)d_in[1];
    const float* W1s  = (const float*)d_in[2];
    const float* b1   = (const float*)d_in[3];
    const float* W2   = (const float*)d_in[4];
    const float* W2s  = (const float*)d_in[5];
    const float* b2   = (const float*)d_in[6];
    const float* fcw  = (const float*)d_in[7];
    const float* fcb  = (const float*)d_in[8];
    const int*   src  = (const int*)d_in[9];
    const int*   dst  = (const int*)d_in[10];
    const int*   et   = (const int*)d_in[11];
    float* out = (float*)d_out;

    cudaFuncSetAttribute(k_fused, cudaFuncAttributeMaxDynamicSharedMemorySize, GEMM_SMEM);

    const int grid = (NN + 127) / 128;   // 391

    k_setup<<<SETUP_GRID, 256>>>(in_feat, W1, W1s, W2, W2s);
    k_hist<<<(NE + 255) / 256, 256>>>(dst, et);
    k_scan1<<<NB, 1024>>>();
    k_scan2<<<1, 512>>>();
    k_scan3<<<NB, 1024>>>();
    k_scatter<<<(NE + 255) / 256, 256>>>(src, dst, et);
    k_fused<<<grid, 512, GEMM_SMEM>>>(b1, 0);
    k_fused<<<grid, 512, GEMM_SMEM>>>(b2, 1);
    k_final<<<1, 128>>>(fcw, fcb, out);
}

// round 12
// speedup vs baseline: 2.6802x; 1.0150x over previous
#include <cuda_runtime.h>
#include <cuda_bf16.h>
#include <mma.h>
#include <math.h>
#include <cstdint>

using namespace nvcuda;

// Problem constants
#define NN 50000
#define NE 800000
#define F  128
#define R  8
#define NKEY (NN * R)                // 400000 (rel,dst) buckets, key = rel*NN + dst

// smem tile row: 136 bf16 = 272 bytes -> LDSM rows hit banks 4r mod 32 (conflict-free)
#define PADC 136
#define ROW2W 34                     // uint2 per padded weight row
#define ROWB (PADC * 2)              // 272 bytes
#define TILEB (128 * ROWB)           // 34816 bytes per 128-row tile
#define STAGEB (2 * TILEB)           // A + B per stage = 69632
#define GEMM_SMEM (2 * STAGEB + 64)  // 2 stages + mbarriers = 139328

// ---------------- device scratch (no cudaMalloc allowed) ----------------
// h arrays DENSE 128 cols (256B-aligned rows)
__device__ __nv_bfloat16 g_h1[(size_t)NN * F];
__device__ __nv_bfloat16 g_hbf[(size_t)NN * F];
__device__ __nv_bfloat16 g_Wb1[9 * 128 * PADC];   // W1 blocks (+self), padded rows
__device__ __nv_bfloat16 g_Wb2[9 * 128 * PADC];
__device__ int      g_deg2[NKEY];                 // zero at entry (static init / re-zeroed by fused L1)
__device__ int      g_off2[NKEY + 1];
__device__ int      g_cur2[NKEY];
__device__ int      g_bsum[128];
__device__ int      g_boff[128];
__device__ int      g_tick;                       // reset by k_scatter
__device__ volatile int g_flag;                   // reset by k_scatter
__device__ uint32_t g_epack[NE];                  // src | dst<<16, sorted by (rel,dst)
__device__ float    g_pool[F];                    // zeroed by k_final after use

// ---------------- PTX helpers ----------------
__device__ __forceinline__ void mbar_init(uint32_t mbar, uint32_t cnt) {
    asm volatile("mbarrier.init.shared.b64 [%0], %1;" :: "r"(mbar), "r"(cnt) : "memory");
}
__device__ __forceinline__ void mbar_arrive(uint32_t mbar) {
    asm volatile("mbarrier.arrive.release.cta.shared::cta.b64 _, [%0];" :: "r"(mbar) : "memory");
}
__device__ __forceinline__ void mbar_arrive_expect_tx(uint32_t mbar, uint32_t bytes) {
    asm volatile("mbarrier.arrive.expect_tx.shared.b64 _, [%0], %1;"
                 :: "r"(mbar), "r"(bytes) : "memory");
}
__device__ __forceinline__ void mbar_wait(uint32_t mbar, uint32_t parity) {
    asm volatile(
        "{\n\t.reg .pred P;\n\t"
        "W%=:\n\t"
        "mbarrier.try_wait.parity.acquire.cta.shared::cta.b64 P, [%0], %1, 0x989680;\n\t"
        "@!P bra.uni W%=;\n\t}"
        :: "r"(mbar), "r"(parity) : "memory");
}
__device__ __forceinline__ void bulk_g2s(uint32_t sdst, const void* gsrc, uint32_t bytes,
                                         uint32_t mbar) {
    asm volatile(
        "cp.async.bulk.shared::cta.global.mbarrier::complete_tx::bytes [%0], [%1], %2, [%3];"
        :: "r"(sdst), "l"(gsrc), "r"(bytes), "r"(mbar) : "memory");
}

// ---------------- launch 1: hist + all fp32->bf16 converts ----------------
#define NH_BLK ((NE + 255) / 256)                // 3125
#define NC_BLK ((NN * F / 4 + 255) / 256)        // 6250
#define NW_ELEM (9 * F * F / 4)                  // 36864 float4 groups
#define NW_BLK ((NW_ELEM + 255) / 256)           // 144
#define FRONT_GRID (NH_BLK + NC_BLK + 2 * NW_BLK)

__global__ void __launch_bounds__(256)
k_front(const float* __restrict__ in_feat,
        const float* __restrict__ W1, const float* __restrict__ W1s,
        const float* __restrict__ W2, const float* __restrict__ W2s,
        const int* __restrict__ dst, const int* __restrict__ et) {
    int b = blockIdx.x;
    int t = threadIdx.x;
    if (b < NH_BLK) {
        int e = b * 256 + t;
        if (e < NE) atomicAdd(&g_deg2[et[e] * NN + dst[e]], 1);
        return;
    }
    b -= NH_BLK;
    if (b < NC_BLK) {
        int i = b * 256 + t;
        if (i >= NN * F / 4) return;
        float4 v = ((const float4*)in_feat)[i];
        __nv_bfloat162 p0 = __floats2bfloat162_rn(v.x, v.y);
        __nv_bfloat162 p1 = __floats2bfloat162_rn(v.z, v.w);
        uint2 o; o.x = *(unsigned*)&p0; o.y = *(unsigned*)&p1;
        ((uint2*)g_hbf)[i] = o;                  // dense rows
        return;
    }
    b -= NC_BLK;
    int which = (b < NW_BLK) ? 0 : 1;
    if (which) b -= NW_BLK;
    int i = b * 256 + t;
    if (i >= NW_ELEM) return;
    const float* W  = which ? W2  : W1;
    const float* Ws = which ? W2s : W1s;
    const float4* src = (i < 8 * F * F / 4) ? ((const float4*)W + i)
                                            : ((const float4*)Ws + (i - 8 * F * F / 4));
    float4 v = *src;
    __nv_bfloat162 p0 = __floats2bfloat162_rn(v.x, v.y);
    __nv_bfloat162 p1 = __floats2bfloat162_rn(v.z, v.w);
    uint2 o; o.x = *(unsigned*)&p0; o.y = *(unsigned*)&p1;
    int row = i >> 5, c4 = i & 31;
    ((uint2*)(which == 0 ? g_Wb1 : g_Wb2))[(size_t)row * ROW2W + c4] = o;   // padded rows
}

// ---------------- launch 2: single-kernel scan (fence-and-flag, 98 resident blocks) ----------------
#define SCAN_BLK 98                              // 98*4096 = 401408 >= 400000; 98 <= 148 SMs

__global__ void __launch_bounds__(1024) k_scan() {
    __shared__ int ws[32];
    __shared__ int s_last;
    int b = blockIdx.x, t = threadIdx.x;
    int lane = t & 31, wid = t >> 5;
    int base = b * 4096 + t * 4;
    int4 v4 = make_int4(0, 0, 0, 0);
    if (base + 3 < NKEY) v4 = *(const int4*)&g_deg2[base];
    else if (base < NKEY) {
        v4.x = g_deg2[base];
        if (base + 1 < NKEY) v4.y = g_deg2[base + 1];
        if (base + 2 < NKEY) v4.z = g_deg2[base + 2];
    }
    int s = v4.x + v4.y + v4.z + v4.w;
    int x = s;
    #pragma unroll
    for (int o = 1; o < 32; o <<= 1) { int u = __shfl_up_sync(~0u, x, o); if (lane >= o) x += u; }
    if (lane == 31) ws[wid] = x;
    __syncthreads();
    if (wid == 0) {
        int w = ws[lane];
        #pragma unroll
        for (int o = 1; o < 32; o <<= 1) { int u = __shfl_up_sync(~0u, w, o); if (lane >= o) w += u; }
        ws[lane] = w;
    }
    __syncthreads();
    int blk_excl = (x - s) + (wid > 0 ? ws[wid - 1] : 0);
    int blk_total = ws[31];
    __syncthreads();
    if (t == 0) {
        g_bsum[b] = blk_total;
        __threadfence();
        int tk = atomicAdd(&g_tick, 1);
        s_last = (tk == SCAN_BLK - 1) ? 1 : 0;
    }
    __syncthreads();
    // last block: single-warp shuffle-only scan of the 98 block sums (NO divergent barriers)
    if (s_last && wid == 0) {
        int v[4]; int psum = 0;
        #pragma unroll
        for (int j = 0; j < 4; j++) {
            int k = lane * 4 + j;
            v[j] = (k < SCAN_BLK) ? g_bsum[k] : 0;
            psum += v[j];
        }
        int xx = psum;
        #pragma unroll
        for (int o = 1; o < 32; o <<= 1) { int u = __shfl_up_sync(~0u, xx, o); if (lane >= o) xx += u; }
        int run = xx - psum;
        #pragma unroll
        for (int j = 0; j < 4; j++) {
            int k = lane * 4 + j;
            if (k < SCAN_BLK) g_boff[k] = run;
            run += v[j];
        }
        if (lane == 31) g_off2[NKEY] = run;
        __syncwarp();
        if (lane == 0) { __threadfence(); g_flag = 1; }
    }
    if (t == 0) { while (g_flag == 0) __nanosleep(64); }
    __syncthreads();
    __threadfence();
    int bb = g_boff[b] + blk_excl;
    int e0 = bb;
    int e1 = e0 + v4.x;
    int e2 = e1 + v4.y;
    int e3 = e2 + v4.z;
    if (base + 3 < NKEY) {
        *(int4*)&g_off2[base] = make_int4(e0, e1, e2, e3);
        *(int4*)&g_cur2[base] = make_int4(e0, e1, e2, e3);
    } else if (base < NKEY) {
        g_off2[base] = e0; g_cur2[base] = e0;
        if (base + 1 < NKEY) { g_off2[base + 1] = e1; g_cur2[base + 1] = e1; }
        if (base + 2 < NKEY) { g_off2[base + 2] = e2; g_cur2[base + 2] = e2; }
    }
}

// ---------------- launch 3: scatter (+ reset scan flags) ----------------
__global__ void k_scatter(const int* __restrict__ src, const int* __restrict__ dst,
                          const int* __restrict__ et) {
    if (blockIdx.x == 0 && threadIdx.x == 0) { g_tick = 0; g_flag = 0; }
    int e = blockIdx.x * blockDim.x + threadIdx.x;
    if (e < NE) {
        int d = dst[e];
        int p = atomicAdd(&g_cur2[et[e] * NN + d], 1);
        g_epack[p] = (uint32_t)src[e] | ((uint32_t)d << 16);
    }
}

// ---------------- launch 4/5: fused gather + GEMM + epilogue (warp-specialized) ----------------
// 512 threads: warps 0-7 consumers (wmma), warps 8-15 producers (gather).
__global__ void __launch_bounds__(512)
k_fused(const float* __restrict__ bias, int layer) {
    extern __shared__ char smraw[];
    uint32_t sbase = (uint32_t)__cvta_generic_to_shared(smraw);
    const __nv_bfloat16* hinp = layer ? g_h1 : g_hbf;
    const uint2* hin4 = (const uint2*)hinp;       // dense: 32 uint2 per row
    const __nv_bfloat16* Wb = layer ? g_Wb2 : g_Wb1;
    int m0 = blockIdx.x * 128;
    int t = threadIdx.x;
    int warp = t >> 5, lane = t & 31;
    uint32_t mbF0 = sbase + 2 * STAGEB;           // full[0], full[1]
    uint32_t mbE0 = mbF0 + 16;                    // empty[0], empty[1]

    if (t == 0) {
        mbar_init(mbF0, 257);     mbar_init(mbF0 + 8, 257);
        mbar_init(mbE0, 256);     mbar_init(mbE0 + 8, 256);
    }
    __syncthreads();

    if (warp < 8) {
        // ---------------- consumer ----------------
        int wm = warp >> 2;      // 0..1 (64-row tiles)
        int wn = warp & 3;       // 0..3 (32-col tiles)
        wmma::fragment<wmma::accumulator, 16, 16, 16, float> c[4][2];
        #pragma unroll
        for (int i = 0; i < 4; i++)
            #pragma unroll
            for (int j = 0; j < 2; j++) wmma::fill_fragment(c[i][j], 0.f);

        for (int kb = 0; kb < 9; kb++) {
            int s = kb & 1;
            uint32_t par = (kb >> 1) & 1;
            mbar_wait(mbF0 + 8 * s, par);
            const __nv_bfloat16* sA = (const __nv_bfloat16*)(smraw + s * STAGEB);
            const __nv_bfloat16* sB = sA + 128 * PADC;
            #pragma unroll
            for (int ks = 0; ks < 8; ks++) {
                wmma::fragment<wmma::matrix_b, 16, 16, 16, __nv_bfloat16, wmma::row_major> bf[2];
                #pragma unroll
                for (int j = 0; j < 2; j++)
                    wmma::load_matrix_sync(bf[j], sB + (ks * 16) * PADC + wn * 32 + j * 16, PADC);
                #pragma unroll
                for (int i = 0; i < 4; i++) {
                    wmma::fragment<wmma::matrix_a, 16, 16, 16, __nv_bfloat16, wmma::row_major> af;
                    wmma::load_matrix_sync(af, sA + (wm * 64 + i * 16) * PADC + ks * 16, PADC);
                    #pragma unroll
                    for (int j = 0; j < 2; j++)
                        wmma::mma_sync(c[i][j], af, bf[j], c[i][j]);
                }
            }
            mbar_arrive(mbE0 + 8 * s);
        }
        __syncthreads();
        float* sC = (float*)smraw;
        #pragma unroll
        for (int i = 0; i < 4; i++)
            #pragma unroll
            for (int j = 0; j < 2; j++)
                wmma::store_matrix_sync(sC + (wm * 64 + i * 16) * 132 + wn * 32 + j * 16,
                                        c[i][j], 132, wmma::mem_row_major);
    } else {
        // ---------------- producer ----------------
        int pw = warp - 8;                        // 0..7, owns rows pw*16..pw*16+15
        int nn = NN - m0; if (nn > 128) nn = 128;
        for (int kb = 0; kb < 9; kb++) {
            int s = kb & 1;
            uint32_t par = ((kb >> 1) & 1) ^ 1;
            mbar_wait(mbE0 + 8 * s, par);
            uint32_t mbF = mbF0 + 8 * s;
            char* sAp = smraw + s * STAGEB;
            if (t == 256) {
                mbar_arrive_expect_tx(mbF, TILEB);
                bulk_g2s(sbase + s * STAGEB + TILEB,
                         (const void*)(Wb + (size_t)kb * 128 * PADC), TILEB, mbF);
            }
            if (kb < 8) {
                // zero my 16 rows (lane's 8-byte slot)
                #pragma unroll
                for (int r = 0; r < 16; r++)
                    *(uint2*)(sAp + (pw * 16 + r) * ROWB + lane * 8) = make_uint2(0u, 0u);
                int nbeg = pw * 16;
                int nend = nbeg + 16; if (nend > nn) nend = nn;
                if (nbeg < nend) {
                    int wb = g_off2[kb * NN + m0 + nbeg];
                    int we = g_off2[kb * NN + m0 + nend];
                    int cur = -1;
                    float a0 = 0.f, a1 = 0.f, a2 = 0.f, a3 = 0.f;
                    for (int e = wb; e < we; e += 32) {
                        uint32_t pk = 0xFFFF0000u;               // sentinel dst
                        if (e + lane < we) pk = g_epack[e + lane];
                        int ccnt = we - e; if (ccnt > 32) ccnt = 32;
                        for (int g = 0; g < ccnt; g += 8) {
                            uint2 rr[8]; int dd[8];
                            #pragma unroll
                            for (int j = 0; j < 8; j++) {
                                uint32_t p = __shfl_sync(0xffffffffu, pk, g + j);
                                dd[j] = (int)(p >> 16);
                                rr[j] = hin4[(size_t)(p & 0xFFFFu) * 32 + lane];
                            }
                            #pragma unroll
                            for (int j = 0; j < 8; j++) {
                                if (dd[j] == 0xFFFF) continue;
                                if (dd[j] != cur) {
                                    if (cur >= 0) {
                                        __nv_bfloat162 o0 = __floats2bfloat162_rn(a0, a1);
                                        __nv_bfloat162 o1 = __floats2bfloat162_rn(a2, a3);
                                        *(uint2*)(sAp + (cur - m0) * ROWB + lane * 8) =
                                            make_uint2(*(unsigned*)&o0, *(unsigned*)&o1);
                                    }
                                    cur = dd[j];
                                    a0 = a1 = a2 = a3 = 0.f;
                                }
                                __nv_bfloat162 p0 = *(__nv_bfloat162*)&rr[j].x;
                                __nv_bfloat162 p1 = *(__nv_bfloat162*)&rr[j].y;
                                float2 f0 = __bfloat1622float2(p0);
                                float2 f1 = __bfloat1622float2(p1);
                                a0 += f0.x; a1 += f0.y; a2 += f1.x; a3 += f1.y;
                            }
                        }
                    }
                    if (cur >= 0) {
                        __nv_bfloat162 o0 = __floats2bfloat162_rn(a0, a1);
                        __nv_bfloat162 o1 = __floats2bfloat162_rn(a2, a3);
                        *(uint2*)(sAp + (cur - m0) * ROWB + lane * 8) =
                            make_uint2(*(unsigned*)&o0, *(unsigned*)&o1);
                    }
                }
            } else {
                // self-loop stage: copy my 16 h rows into sA (dense gmem -> padded smem)
                #pragma unroll
                for (int r = 0; r < 16; r++) {
                    int row = pw * 16 + r;
                    int gr = m0 + row;
                    uint2 v = (gr < NN) ? hin4[(size_t)gr * 32 + lane] : make_uint2(0u, 0u);
                    *(uint2*)(sAp + row * ROWB + lane * 8) = v;
                }
            }
            mbar_arrive(mbF);
        }
        __syncthreads();
    }
    __syncthreads();

    // ---------------- epilogue (all 512 threads) ----------------
    float* sC = (float*)smraw;
    if (layer == 0) {
        #pragma unroll
        for (int i = 0; i < 8; i++) {
            int idx = t + i * 512;
            int row = idx >> 5;
            int c4  = idx & 31;
            if (m0 + row < NN) {
                float* sp = sC + row * 132 + c4 * 4;
                float x = fmaxf(sp[0] + bias[c4 * 4 + 0], 0.f);
                float y = fmaxf(sp[1] + bias[c4 * 4 + 1], 0.f);
                float z = fmaxf(sp[2] + bias[c4 * 4 + 2], 0.f);
                float w = fmaxf(sp[3] + bias[c4 * 4 + 3], 0.f);
                __nv_bfloat162 p0 = __floats2bfloat162_rn(x, y);
                __nv_bfloat162 p1 = __floats2bfloat162_rn(z, w);
                uint2 o; o.x = *(unsigned*)&p0; o.y = *(unsigned*)&p1;
                ((uint2*)g_h1)[(size_t)(m0 + row) * 32 + c4] = o;
            }
        }
    } else {
        int col = t & 127;
        int rg = t >> 7;
        float bc = bias[col];
        float s = 0.f;
        for (int r = rg * 32; r < rg * 32 + 32; r++) {
            if (m0 + r < NN) s += fmaxf(sC[r * 132 + col] + bc, 0.f);
        }
        atomicAdd(&g_pool[col], s);
        // re-zero g_deg2 for the next replay (each thread: one int2)
        int gid = blockIdx.x * 512 + t;
        if (gid < NKEY / 2) ((int2*)g_deg2)[gid] = make_int2(0, 0);
    }
}

// ---------------- launch 6: final (+ re-zero pool) ----------------
__global__ void k_final(const float* __restrict__ fc_w, const float* __restrict__ fc_b,
                        float* __restrict__ out) {
    __shared__ float red[F];
    int t = threadIdx.x;
    red[t] = g_pool[t] * (1.f / (float)NN) * fc_w[t];
    __syncthreads();
    for (int o = 64; o > 0; o >>= 1) {
        if (t < o) red[t] += red[t + o];
        __syncthreads();
    }
    if (t == 0) {
        float logit = red[0] + fc_b[0];
        out[0] = 1.f / (1.f + expf(-logit));
    }
    g_pool[t] = 0.f;
}

// ---------------- launch ----------------
extern "C" void kernel_launch(void* const* d_in, const int* in_sizes, int n_in,
                              void* d_out, int out_size) {
    const float* in_feat = (const float*)d_in[0];
    const float* W1   = (const float*)d_in[1];
    const float* W1s  = (const float*)d_in[2];
    const float* b1   = (const float*)d_in[3];
    const float* W2   = (const float*)d_in[4];
    const float* W2s  = (const float*)d_in[5];
    const float* b2   = (const float*)d_in[6];
    const float* fcw  = (const float*)d_in[7];
    const float* fcb  = (const float*)d_in[8];
    const int*   src  = (const int*)d_in[9];
    const int*   dst  = (const int*)d_in[10];
    const int*   et   = (const int*)d_in[11];
    float* out = (float*)d_out;

    cudaFuncSetAttribute(k_fused, cudaFuncAttributeMaxDynamicSharedMemorySize, GEMM_SMEM);

    const int grid = (NN + 127) / 128;   // 391

    k_front<<<FRONT_GRID, 256>>>(in_feat, W1, W1s, W2, W2s, dst, et);   // 1
    k_scan<<<SCAN_BLK, 1024>>>();                                       // 2
    k_scatter<<<(NE + 255) / 256, 256>>>(src, dst, et);                 // 3
    k_fused<<<grid, 512, GEMM_SMEM>>>(b1, 0);                           // 4  <- ncu target
    k_fused<<<grid, 512, GEMM_SMEM>>>(b2, 1);                           // 5
    k_final<<<1, 128>>>(fcw, fcb, out);                                 // 6
}